// round 7
// baseline (speedup 1.0000x reference)
#include <cuda_runtime.h>
#include <cstdint>

#define HMAX 60
#define GDIM 121           // 2*HMAX+1
#define MAX_MULT 5
#define RCP_WMIN (1.0f / 0.95f)
#define RCP_WMAX 0.8f      // 1/1.25
#define BLK 256
#define HKL_MAX 12         // dataset bound on |h|,|k|,|l|

__device__ __forceinline__ int gcd_loop(int a, int b) {
    while (b != 0) { int t = a % b; a = b; b = t; }
    return a;
}

__global__ void __launch_bounds__(BLK)
expand_harmonics_kernel(const int* __restrict__ asu_id,       // [N]
                        const int* __restrict__ hkl,          // [N,3]
                        const float* __restrict__ wavelength, // [N]
                        const float* __restrict__ dmin,       // [N_ASU]
                        const float* __restrict__ B,          // [N_ASU,3,3]
                        const int* __restrict__ refl_table,   // [N_ASU,G,G,G]
                        float* __restrict__ out,              // [30*N] f32
                        int N)
{
    __shared__ __align__(16) float s_hkl[BLK * 15];
    __shared__ __align__(16) float s_wl [BLK * 5];
    __shared__ __align__(16) float s_d  [BLK * 5];
    __shared__ __align__(16) float s_rid[BLK * 5];
    __shared__ unsigned char s_gcd[13 * 13];   // gcd table for 0..12
    __shared__ float s_recip[32];              // 1/i (rn), i=1..31; [0]=0

    const int t  = threadIdx.x;
    const int i0 = blockIdx.x * BLK;
    const int i  = i0 + t;
    const int cnt = min(BLK, N - i0);          // rows in this block (>=1)
    const bool active = t < cnt;

    // Build LUTs once per block
    if (t < 169) {
        int a = t / 13, b = t % 13;
        s_gcd[t] = (unsigned char)gcd_loop(a, b);
    }
    if (t < 32) {
        s_recip[t] = (t == 0) ? 0.0f : __frcp_rn((float)t);
    }

    // Stage hkl through shared (coalesced), reusing s_hkl as int scratch
    int* s_in = (int*)s_hkl;
    {
        const int n3 = cnt * 3;
        const int base = i0 * 3;
        for (int idx = t; idx < n3; idx += BLK)
            s_in[idx] = hkl[base + idx];
    }
    __syncthreads();

    // ---- per-thread compute, registers only (s_in still live) ----
    bool  mask = false;
    float h0f = 0.f, k0f = 0.f, l0f = 0.f, wl0 = 0.f, d0 = 0.f;
    float n_max = 0.f, n_min = 0.f;
    int   center = 0, step = 0, max_abs = 0;

    if (active) {
        const int asu = asu_id[i];
        const int h = s_in[3 * t + 0];
        const int k = s_in[3 * t + 1];
        const int l = s_in[3 * t + 2];
        mask = (h | k | l) != 0;

        const int ah = abs(h), ak = abs(k), al = abs(l);

        int g;
        if (max(max(ah, ak), al) <= HKL_MAX) {
            const int g1 = s_gcd[ah * 13 + ak];
            g = s_gcd[g1 * 13 + al];
        } else {
            g = gcd_loop(gcd_loop(ah, ak), al);   // safety fallback
        }
        const int ns = max(g, 1);
        const float rns = s_recip[ns & 31];

        // Exact integer quotients via round-to-nearest
        const int h0 = __float2int_rn((float)h * rns);
        const int k0 = __float2int_rn((float)k * rns);
        const int l0 = __float2int_rn((float)l * rns);

        wl0 = wavelength[i] * (float)ns;

        const float* Ba = B + 9 * asu;
        h0f = (float)h0; k0f = (float)k0; l0f = (float)l0;
        const float s0 = __ldg(&Ba[0]) * h0f + __ldg(&Ba[1]) * k0f + __ldg(&Ba[2]) * l0f;
        const float s1 = __ldg(&Ba[3]) * h0f + __ldg(&Ba[4]) * k0f + __ldg(&Ba[5]) * l0f;
        const float s2 = __ldg(&Ba[6]) * h0f + __ldg(&Ba[7]) * k0f + __ldg(&Ba[8]) * l0f;
        const float nrm = __fsqrt_rn(s0 * s0 + s1 * s1 + s2 * s2);
        d0 = __fdividef(1.0f, fmaxf(nrm, 1e-6f));

        n_max = fminf(floorf(__fdividef(d0, __ldg(&dmin[asu]))),
                      floorf(wl0 * RCP_WMIN));
        n_min = floorf(wl0 * RCP_WMAX) + 1.0f;

        center = asu * (GDIM * GDIM * GDIM)
               + (HMAX * GDIM + HMAX) * GDIM + HMAX;
        step = h0 * (GDIM * GDIM) + k0 * GDIM + l0;
        max_abs = max(max(abs(h0), abs(k0)), abs(l0));
    }

    __syncthreads();   // s_in dead; s_hkl becomes output staging

    if (active) {
#pragma unroll
        for (int m = 0; m < MAX_MULT; ++m) {
            float na = n_min + (float)m;
            na = (na > n_max) ? 0.0f : na;
            int ni = (int)na;                 // integral, 0..~18

            const bool valid = (max_abs * ni) <= HMAX;
            int rid = -1;
            if (valid) rid = __ldg(&refl_table[center + ni * step]);

            const bool present = rid >= 0;
            const float n_inv = present ? s_recip[ni & 31] : 0.0f;
            const float haf = present ? h0f * na : 0.0f;
            const float kaf = present ? k0f * na : 0.0f;
            const float laf = present ? l0f * na : 0.0f;

            s_hkl[t * 15 + m * 3 + 0] = haf;
            s_hkl[t * 15 + m * 3 + 1] = kaf;
            s_hkl[t * 15 + m * 3 + 2] = laf;
            s_wl [t * 5 + m] = wl0 * n_inv;
            s_d  [t * 5 + m] = d0  * n_inv;
            s_rid[t * 5 + m] = mask ? (float)rid : 0.0f;
        }
    }

    __syncthreads();

    const long long nll = (long long)N;
    float* __restrict__ g_hkl = out + (long long)i0 * 15;
    float* __restrict__ g_wl  = out + 15 * nll + (long long)i0 * 5;
    float* __restrict__ g_d   = out + 20 * nll + (long long)i0 * 5;
    float* __restrict__ g_rid = out + 25 * nll + (long long)i0 * 5;

    const bool vec_ok = (cnt == BLK) && ((N & 3) == 0) &&
                        ((((uintptr_t)out) & 15) == 0);

    if (vec_ok) {
        const float4* s4h = (const float4*)s_hkl;
        float4* g4h = (float4*)g_hkl;
#pragma unroll
        for (int idx = t; idx < (BLK * 15) / 4; idx += BLK)
            g4h[idx] = s4h[idx];

        const float4* s4w = (const float4*)s_wl;
        const float4* s4d = (const float4*)s_d;
        const float4* s4r = (const float4*)s_rid;
        float4* g4w = (float4*)g_wl;
        float4* g4d = (float4*)g_d;
        float4* g4r = (float4*)g_rid;
#pragma unroll
        for (int idx = t; idx < (BLK * 5) / 4; idx += BLK) {
            g4w[idx] = s4w[idx];
            g4d[idx] = s4d[idx];
            g4r[idx] = s4r[idx];
        }
    } else {
        const int n15 = cnt * 15;
        for (int idx = t; idx < n15; idx += BLK)
            g_hkl[idx] = s_hkl[idx];
        const int n5 = cnt * 5;
        for (int idx = t; idx < n5; idx += BLK) {
            g_wl [idx] = s_wl [idx];
            g_d  [idx] = s_d  [idx];
            g_rid[idx] = s_rid[idx];
        }
    }
}

extern "C" void kernel_launch(void* const* d_in, const int* in_sizes, int n_in,
                              void* d_out, int out_size)
{
    const int*   asu_id     = (const int*)d_in[0];
    const int*   hkl        = (const int*)d_in[1];
    const float* wavelength = (const float*)d_in[2];
    const float* dmin       = (const float*)d_in[3];
    const float* B          = (const float*)d_in[4];
    const int*   refl_table = (const int*)d_in[5];

    const int N = in_sizes[0];
    float* out = (float*)d_out;

    const int blocks = (N + BLK - 1) / BLK;
    expand_harmonics_kernel<<<blocks, BLK>>>(asu_id, hkl, wavelength,
                                             dmin, B, refl_table, out, N);
}

// round 8
// speedup vs baseline: 1.2314x; 1.2314x over previous
#include <cuda_runtime.h>
#include <cstdint>

#define HMAX 60
#define GDIM 121           // 2*HMAX+1
#define MAX_MULT 5
#define RCP_WMIN (1.0f / 0.95f)
#define RCP_WMAX 0.8f      // 1/1.25
#define BLK 256
#define HKL_MAX 12         // dataset bound on |h|,|k|,|l|

__device__ __forceinline__ int gcd_loop(int a, int b) {
    while (b != 0) { int t = a % b; a = b; b = t; }
    return a;
}

__global__ void __launch_bounds__(BLK)
expand_harmonics_kernel(const int* __restrict__ asu_id,       // [N]
                        const int* __restrict__ hkl,          // [N,3]
                        const float* __restrict__ wavelength, // [N]
                        const float* __restrict__ dmin,       // [N_ASU]
                        const float* __restrict__ B,          // [N_ASU,3,3]
                        const int* __restrict__ refl_table,   // [N_ASU,G,G,G]
                        float* __restrict__ out,              // [30*N] f32
                        int N)
{
    __shared__ __align__(16) float s_hkl[BLK * 15];
    __shared__ __align__(16) float s_wl [BLK * 5];
    __shared__ __align__(16) float s_d  [BLK * 5];
    __shared__ __align__(16) float s_rid[BLK * 5];
    __shared__ unsigned char s_gcd[13 * 13];   // gcd table for 0..12
    __shared__ float s_recip[32];              // 1/i (rn), i=1..31; [0]=0

    const int t  = threadIdx.x;
    const int i0 = blockIdx.x * BLK;
    const int i  = i0 + t;

    // Build tables (cheap, once per block, overlapped with input loads)
    if (t < 169) {
        int a = t / 13, b = t % 13;
        s_gcd[t] = (unsigned char)gcd_loop(a, b);
    }
    if (t < 32) {
        s_recip[t] = (t == 0) ? 0.0f : __frcp_rn((float)t); // exact rn recip
    }
    __syncthreads();

    if (i < N) {
        const int asu = asu_id[i];
        const int h = hkl[3 * i + 0];
        const int k = hkl[3 * i + 1];
        const int l = hkl[3 * i + 2];
        const bool mask = (h | k | l) != 0;

        const int ah = abs(h), ak = abs(k), al = abs(l);

        int g;
        if (max(max(ah, ak), al) <= HKL_MAX) {
            const int g1 = s_gcd[ah * 13 + ak];
            g = s_gcd[g1 * 13 + al];
        } else {
            g = gcd_loop(gcd_loop(ah, ak), al);   // never taken for this dataset
        }
        const int ns = max(g, 1);
        const float rns = s_recip[ns & 31];

        // Exact integer quotients recovered via round-to-nearest
        const int h0 = __float2int_rn((float)h * rns);
        const int k0 = __float2int_rn((float)k * rns);
        const int l0 = __float2int_rn((float)l * rns);

        const float wl0 = wavelength[i] * (float)ns;

        const float* Ba = B + 9 * asu;
        const float h0f = (float)h0, k0f = (float)k0, l0f = (float)l0;
        const float s0 = __ldg(&Ba[0]) * h0f + __ldg(&Ba[1]) * k0f + __ldg(&Ba[2]) * l0f;
        const float s1 = __ldg(&Ba[3]) * h0f + __ldg(&Ba[4]) * k0f + __ldg(&Ba[5]) * l0f;
        const float s2 = __ldg(&Ba[6]) * h0f + __ldg(&Ba[7]) * k0f + __ldg(&Ba[8]) * l0f;
        const float nrm = __fsqrt_rn(s0 * s0 + s1 * s1 + s2 * s2);
        const float d0  = __fdividef(1.0f, fmaxf(nrm, 1e-6f));

        const float n_max = fminf(floorf(__fdividef(d0, __ldg(&dmin[asu]))),
                                  floorf(wl0 * RCP_WMIN));
        const float n_min = floorf(wl0 * RCP_WMAX) + 1.0f;

        const int center = asu * (GDIM * GDIM * GDIM)
                         + (HMAX * GDIM + HMAX) * GDIM + HMAX;
        const int step = h0 * (GDIM * GDIM) + k0 * GDIM + l0;
        const int max_abs = max(max(abs(h0), abs(k0)), abs(l0));

#pragma unroll
        for (int m = 0; m < MAX_MULT; ++m) {
            float na = n_min + (float)m;
            na = (na > n_max) ? 0.0f : na;
            int ni = (int)na;                 // integral, 0..~18

            const bool valid = (max_abs * ni) <= HMAX;
            int rid = -1;
            if (valid) rid = __ldg(&refl_table[center + ni * step]);

            const bool present = rid >= 0;
            const float n_inv = present ? s_recip[ni & 31] : 0.0f;
            const float haf = present ? h0f * na : 0.0f;
            const float kaf = present ? k0f * na : 0.0f;
            const float laf = present ? l0f * na : 0.0f;

            s_hkl[t * 15 + m * 3 + 0] = haf;
            s_hkl[t * 15 + m * 3 + 1] = kaf;
            s_hkl[t * 15 + m * 3 + 2] = laf;
            s_wl [t * 5 + m] = wl0 * n_inv;
            s_d  [t * 5 + m] = d0  * n_inv;
            s_rid[t * 5 + m] = mask ? (float)rid : 0.0f;
        }
    }

    __syncthreads();

    const int cnt = min(BLK, N - i0);
    if (cnt <= 0) return;

    const long long nll = (long long)N;
    float* __restrict__ g_hkl = out + (long long)i0 * 15;
    float* __restrict__ g_wl  = out + 15 * nll + (long long)i0 * 5;
    float* __restrict__ g_d   = out + 20 * nll + (long long)i0 * 5;
    float* __restrict__ g_rid = out + 25 * nll + (long long)i0 * 5;

    const bool vec_ok = (cnt == BLK) && ((N & 3) == 0) &&
                        ((((uintptr_t)out) & 15) == 0);

    if (vec_ok) {
        const float4* s4h = (const float4*)s_hkl;
        float4* g4h = (float4*)g_hkl;
#pragma unroll
        for (int idx = t; idx < (BLK * 15) / 4; idx += BLK)
            g4h[idx] = s4h[idx];

        const float4* s4w = (const float4*)s_wl;
        const float4* s4d = (const float4*)s_d;
        const float4* s4r = (const float4*)s_rid;
        float4* g4w = (float4*)g_wl;
        float4* g4d = (float4*)g_d;
        float4* g4r = (float4*)g_rid;
#pragma unroll
        for (int idx = t; idx < (BLK * 5) / 4; idx += BLK) {
            g4w[idx] = s4w[idx];
            g4d[idx] = s4d[idx];
            g4r[idx] = s4r[idx];
        }
    } else {
        const int n15 = cnt * 15;
        for (int idx = t; idx < n15; idx += BLK)
            g_hkl[idx] = s_hkl[idx];
        const int n5 = cnt * 5;
        for (int idx = t; idx < n5; idx += BLK) {
            g_wl [idx] = s_wl [idx];
            g_d  [idx] = s_d  [idx];
            g_rid[idx] = s_rid[idx];
        }
    }
}

extern "C" void kernel_launch(void* const* d_in, const int* in_sizes, int n_in,
                              void* d_out, int out_size)
{
    const int*   asu_id     = (const int*)d_in[0];
    const int*   hkl        = (const int*)d_in[1];
    const float* wavelength = (const float*)d_in[2];
    const float* dmin       = (const float*)d_in[3];
    const float* B          = (const float*)d_in[4];
    const int*   refl_table = (const int*)d_in[5];

    const int N = in_sizes[0];
    float* out = (float*)d_out;

    const int blocks = (N + BLK - 1) / BLK;
    expand_harmonics_kernel<<<blocks, BLK>>>(asu_id, hkl, wavelength,
                                             dmin, B, refl_table, out, N);
}

// round 10
// speedup vs baseline: 1.2687x; 1.0303x over previous
#include <cuda_runtime.h>
#include <cstdint>

#define HMAX 60
#define GDIM 121           // 2*HMAX+1
#define MAX_MULT 5
#define RCP_WMIN (1.0f / 0.95f)
#define RCP_WMAX 0.8f      // 1/1.25
#define BLK 256
#define HKL_MAX 12         // dataset bound on |h|,|k|,|l|

__device__ __forceinline__ int gcd_loop(int a, int b) {
    while (b != 0) { int t = a % b; a = b; b = t; }
    return a;
}

__device__ __forceinline__ uint32_t smem_u32(const void* p) {
    uint32_t a;
    asm("{ .reg .u64 t; cvta.to.shared.u64 t, %1; cvt.u32.u64 %0, t; }"
        : "=r"(a) : "l"(p));
    return a;
}

__device__ __forceinline__ void bulk_store(void* gptr, uint32_t saddr, uint32_t bytes) {
    asm volatile("cp.async.bulk.global.shared::cta.bulk_group [%0], [%1], %2;"
                 :: "l"(gptr), "r"(saddr), "r"(bytes) : "memory");
}

__global__ void __launch_bounds__(BLK)
expand_harmonics_kernel(const int* __restrict__ asu_id,       // [N]
                        const int* __restrict__ hkl,          // [N,3]
                        const float* __restrict__ wavelength, // [N]
                        const float* __restrict__ dmin,       // [N_ASU]
                        const float* __restrict__ B,          // [N_ASU,3,3]
                        const int* __restrict__ refl_table,   // [N_ASU,G,G,G]
                        float* __restrict__ out,              // [30*N] f32
                        int N)
{
    __shared__ __align__(16) float s_hkl[BLK * 15];
    __shared__ __align__(16) float s_wl [BLK * 5];
    __shared__ __align__(16) float s_d  [BLK * 5];
    __shared__ __align__(16) float s_rid[BLK * 5];
    __shared__ unsigned char s_gcd[13 * 13];   // gcd table for 0..12
    __shared__ float s_recip[32];              // 1/i (rn), i=1..31; [0]=0

    const int t  = threadIdx.x;
    const int i0 = blockIdx.x * BLK;
    const int i  = i0 + t;

    if (t < 169) {
        int a = t / 13, b = t % 13;
        s_gcd[t] = (unsigned char)gcd_loop(a, b);
    }
    if (t < 32) {
        s_recip[t] = (t == 0) ? 0.0f : __frcp_rn((float)t);
    }
    __syncthreads();

    if (i < N) {
        const int asu = asu_id[i];
        const int h = hkl[3 * i + 0];
        const int k = hkl[3 * i + 1];
        const int l = hkl[3 * i + 2];
        const bool mask = (h | k | l) != 0;

        const int ah = abs(h), ak = abs(k), al = abs(l);

        int g;
        if (max(max(ah, ak), al) <= HKL_MAX) {
            const int g1 = s_gcd[ah * 13 + ak];
            g = s_gcd[g1 * 13 + al];
        } else {
            g = gcd_loop(gcd_loop(ah, ak), al);   // never taken for this dataset
        }
        const int ns = max(g, 1);
        const float rns = s_recip[ns & 31];

        const int h0 = __float2int_rn((float)h * rns);
        const int k0 = __float2int_rn((float)k * rns);
        const int l0 = __float2int_rn((float)l * rns);

        const float wl0 = wavelength[i] * (float)ns;

        const float* Ba = B + 9 * asu;
        const float h0f = (float)h0, k0f = (float)k0, l0f = (float)l0;
        const float s0 = __ldg(&Ba[0]) * h0f + __ldg(&Ba[1]) * k0f + __ldg(&Ba[2]) * l0f;
        const float s1 = __ldg(&Ba[3]) * h0f + __ldg(&Ba[4]) * k0f + __ldg(&Ba[5]) * l0f;
        const float s2 = __ldg(&Ba[6]) * h0f + __ldg(&Ba[7]) * k0f + __ldg(&Ba[8]) * l0f;
        const float nrm = __fsqrt_rn(s0 * s0 + s1 * s1 + s2 * s2);
        const float d0  = __fdividef(1.0f, fmaxf(nrm, 1e-6f));

        const float n_max = fminf(floorf(__fdividef(d0, __ldg(&dmin[asu]))),
                                  floorf(wl0 * RCP_WMIN));
        const float n_min = floorf(wl0 * RCP_WMAX) + 1.0f;

        const int center = asu * (GDIM * GDIM * GDIM)
                         + (HMAX * GDIM + HMAX) * GDIM + HMAX;
        const int step = h0 * (GDIM * GDIM) + k0 * GDIM + l0;
        const int max_abs = max(max(abs(h0), abs(k0)), abs(l0));

#pragma unroll
        for (int m = 0; m < MAX_MULT; ++m) {
            float na = n_min + (float)m;
            na = (na > n_max) ? 0.0f : na;
            int ni = (int)na;                 // integral, 0..~18

            const bool valid = (max_abs * ni) <= HMAX;
            int rid = -1;
            if (valid) rid = __ldg(&refl_table[center + ni * step]);

            const bool present = rid >= 0;
            const float n_inv = present ? s_recip[ni & 31] : 0.0f;
            const float haf = present ? h0f * na : 0.0f;
            const float kaf = present ? k0f * na : 0.0f;
            const float laf = present ? l0f * na : 0.0f;

            s_hkl[t * 15 + m * 3 + 0] = haf;
            s_hkl[t * 15 + m * 3 + 1] = kaf;
            s_hkl[t * 15 + m * 3 + 2] = laf;
            s_wl [t * 5 + m] = wl0 * n_inv;
            s_d  [t * 5 + m] = d0  * n_inv;
            s_rid[t * 5 + m] = mask ? (float)rid : 0.0f;
        }
    }

    __syncthreads();

    const int cnt = min(BLK, N - i0);
    if (cnt <= 0) return;

    const long long nll = (long long)N;
    float* __restrict__ g_hkl = out + (long long)i0 * 15;
    float* __restrict__ g_wl  = out + 15 * nll + (long long)i0 * 5;
    float* __restrict__ g_d   = out + 20 * nll + (long long)i0 * 5;
    float* __restrict__ g_rid = out + 25 * nll + (long long)i0 * 5;

    // TMA bulk-store path: every segment base/size is a 16B multiple when
    // N%4==0 and cnt%4==0 (15*N, 20*N, 25*N, i0*15, i0*5 all *4B align).
    const bool bulk_ok = ((N & 3) == 0) && ((cnt & 3) == 0) &&
                         ((((uintptr_t)out) & 15) == 0);

    if (bulk_ok) {
        if (t == 0) {
            asm volatile("fence.proxy.async.shared::cta;" ::: "memory");
            bulk_store(g_hkl, smem_u32(s_hkl), (uint32_t)cnt * 60u);
            bulk_store(g_wl,  smem_u32(s_wl),  (uint32_t)cnt * 20u);
            bulk_store(g_d,   smem_u32(s_d),   (uint32_t)cnt * 20u);
            bulk_store(g_rid, smem_u32(s_rid), (uint32_t)cnt * 20u);
            asm volatile("cp.async.bulk.commit_group;" ::: "memory");
            asm volatile("cp.async.bulk.wait_group 0;" ::: "memory");
        }
    } else {
        const int n15 = cnt * 15;
        for (int idx = t; idx < n15; idx += BLK)
            g_hkl[idx] = s_hkl[idx];
        const int n5 = cnt * 5;
        for (int idx = t; idx < n5; idx += BLK) {
            g_wl [idx] = s_wl [idx];
            g_d  [idx] = s_d  [idx];
            g_rid[idx] = s_rid[idx];
        }
    }
}

extern "C" void kernel_launch(void* const* d_in, const int* in_sizes, int n_in,
                              void* d_out, int out_size)
{
    const int*   asu_id     = (const int*)d_in[0];
    const int*   hkl        = (const int*)d_in[1];
    const float* wavelength = (const float*)d_in[2];
    const float* dmin       = (const float*)d_in[3];
    const float* B          = (const float*)d_in[4];
    const int*   refl_table = (const int*)d_in[5];

    const int N = in_sizes[0];
    float* out = (float*)d_out;

    const int blocks = (N + BLK - 1) / BLK;
    expand_harmonics_kernel<<<blocks, BLK>>>(asu_id, hkl, wavelength,
                                             dmin, B, refl_table, out, N);
}